// round 13
// baseline (speedup 1.0000x reference)
#include <cuda_runtime.h>
#include <cuda_bf16.h>
#include <cstddef>

#define N_NODES 50000
#define N_EDGES 800000
#define ND_IN   64
#define ED_IN   64
#define HID     128

typedef unsigned long long ull;

#define SCAN_CHUNK 256
#define N_CHUNKS ((N_NODES + SCAN_CHUNK - 1) / SCAN_CHUNK)   // 196

#define NPB      16
#define N_TILES  (N_NODES / NPB)    // 3125
#define PERS_GRID 1184              // 148 SMs * 8 resident blocks

// ---------------- scratch (allocation-free: __device__ globals) ----------------
__device__ int   g_cnt   [N_NODES];
__device__ int   g_rowptr[N_NODES + 1];
__device__ int   g_cursor[N_NODES];
__device__ int   g_part  [N_CHUNKS];
__device__ int   g_tilectr[2];        // work-stealing tile counters (zeroed per replay)
__device__ int   g_eu    [N_EDGES];   // src node per CSR slot
__device__ int   g_ev    [N_EDGES];   // dst node per CSR slot
__device__ int   g_eid   [N_EDGES];   // original edge id per CSR slot
__device__ float g_msum1[(size_t)N_NODES * 128];
__device__ float g_msum2[(size_t)N_NODES * 256];
__device__ float g_hn1  [(size_t)N_NODES * HID];
__device__ float g_P    [(size_t)N_NODES * HID];  // hn @ We_top + be (bias folded)
__device__ float g_Q    [(size_t)N_NODES * HID];  // hn @ We_bot

// ---------------- packed f32x2 helpers ----------------
__device__ __forceinline__ ull pk2(float x, float y) {
    ull r; asm("mov.b64 %0, {%1, %2};" : "=l"(r) : "f"(x), "f"(y)); return r;
}
__device__ __forceinline__ void upk2(ull p, float& x, float& y) {
    asm("mov.b64 {%0, %1}, %2;" : "=f"(x), "=f"(y) : "l"(p));
}
#define FFMA2(d, a, b, c) \
    asm("fma.rn.f32x2 %0, %1, %2, %3;" : "=l"(d) : "l"(a), "l"(b), "l"(c))

// ================= CSR build =================
__global__ void cnt_kernel(const int* __restrict__ v) {
    int e = blockIdx.x * blockDim.x + threadIdx.x;
    if (e < N_EDGES) atomicAdd(&g_cnt[v[e]], 1);
}

// 3-phase parallel scan: chunk reduce -> scan partials (1 block) -> apply
__global__ void part_reduce_kernel() {
    int b = blockIdx.x, t = threadIdx.x;
    int i = b * SCAN_CHUNK + t;
    int x = (i < N_NODES) ? g_cnt[i] : 0;
    __shared__ int ws[8];
    int lane = t & 31, wr = t >> 5;
    #pragma unroll
    for (int d = 16; d > 0; d >>= 1) x += __shfl_down_sync(0xffffffffu, x, d);
    if (lane == 0) ws[wr] = x;
    __syncthreads();
    if (t < 8) {
        int y = ws[t];
        #pragma unroll
        for (int d = 4; d > 0; d >>= 1) y += __shfl_down_sync(0xffu, y, d);
        if (t == 0) g_part[b] = y;
    }
}

__global__ void part_scan_kernel() {
    int t = threadIdx.x;   // 256 threads, N_CHUNKS=196 <= 256
    int x = (t < N_CHUNKS) ? g_part[t] : 0;
    __shared__ int ws[8];
    int lane = t & 31, wr = t >> 5;
    int v = x;
    #pragma unroll
    for (int d = 1; d < 32; d <<= 1) {
        int tt = __shfl_up_sync(0xffffffffu, v, d);
        if (lane >= d) v += tt;
    }
    if (lane == 31) ws[wr] = v;
    __syncthreads();
    if (t < 8) {
        int y = ws[t];
        #pragma unroll
        for (int d = 1; d < 8; d <<= 1) {
            int tt = __shfl_up_sync(0xffu, y, d);
            if (t >= d) y += tt;
        }
        ws[t] = y;
    }
    __syncthreads();
    int incl = v + (wr > 0 ? ws[wr - 1] : 0);
    if (t < N_CHUNKS) g_part[t] = incl - x;           // exclusive chunk offsets
    if (t == N_CHUNKS - 1) g_rowptr[N_NODES] = incl;  // total
}

__global__ void scan_apply_kernel() {
    int b = blockIdx.x, t = threadIdx.x;
    int i = b * SCAN_CHUNK + t;
    int x = (i < N_NODES) ? g_cnt[i] : 0;
    __shared__ int ws[8];
    int lane = t & 31, wr = t >> 5;
    int v = x;
    #pragma unroll
    for (int d = 1; d < 32; d <<= 1) {
        int tt = __shfl_up_sync(0xffffffffu, v, d);
        if (lane >= d) v += tt;
    }
    if (lane == 31) ws[wr] = v;
    __syncthreads();
    if (t < 8) {
        int y = ws[t];
        #pragma unroll
        for (int d = 1; d < 8; d <<= 1) {
            int tt = __shfl_up_sync(0xffu, y, d);
            if (t >= d) y += tt;
        }
        ws[t] = y;
    }
    __syncthreads();
    int excl = v - x + (wr > 0 ? ws[wr - 1] : 0) + g_part[b];
    if (i < N_NODES) {
        g_rowptr[i] = excl;
        g_cursor[i] = excl;   // fill cursors initialized here (no memcpy)
    }
}

__global__ void fill_kernel(const int* __restrict__ u, const int* __restrict__ v) {
    int e = blockIdx.x * blockDim.x + threadIdx.x;
    if (e >= N_EDGES) return;
    int vn = v[e];
    int pos = atomicAdd(&g_cursor[vn], 1);
    g_eu[pos]  = u[e];
    g_ev[pos]  = vn;
    g_eid[pos] = e;
}

// ================= layer-1 aggregation (gather, warp per node, unroll-2) =================
__global__ void __launch_bounds__(256, 8)
agg1_kernel(const float* __restrict__ nf,
            const float* __restrict__ ef) {
    int gtid = blockIdx.x * blockDim.x + threadIdx.x;
    int node = gtid >> 5;
    int lane = gtid & 31;
    if (node >= N_NODES) return;
    int beg = g_rowptr[node], end = g_rowptr[node + 1];
    int c = lane * 4;
    bool isn = (lane < 16);
    const float* base = isn ? nf : ef;
    int coff = isn ? c : (c - ND_IN);
    const int* idxa = isn ? g_eu : g_eid;

    float4 acc = make_float4(0.f, 0.f, 0.f, 0.f);
    int i = beg;
    for (; i + 1 < end; i += 2) {
        int ia = idxa[i];
        int ib = idxa[i + 1];
        float4 t0 = *(const float4*)(base + (size_t)ia * 64 + coff);
        float4 t1 = *(const float4*)(base + (size_t)ib * 64 + coff);
        acc.x += t0.x + t1.x;
        acc.y += t0.y + t1.y;
        acc.z += t0.z + t1.z;
        acc.w += t0.w + t1.w;
    }
    if (i < end) {
        int ia = idxa[i];
        float4 t0 = *(const float4*)(base + (size_t)ia * 64 + coff);
        acc.x += t0.x; acc.y += t0.y; acc.z += t0.z; acc.w += t0.w;
    }
    *(float4*)&g_msum1[(size_t)node * 128 + c] = acc;
}

// ================= layer-2 aggregation, H/E split: 2 warps per node =================
__global__ void __launch_bounds__(256, 8)
agg2_kernel() {
    int gtid = blockIdx.x * blockDim.x + threadIdx.x;
    int warp = gtid >> 5;
    int lane = gtid & 31;
    int node = warp >> 1;
    int half = warp & 1;
    if (node >= N_NODES) return;
    int beg = g_rowptr[node], end = g_rowptr[node + 1];
    int c = lane * 4;

    if (half == 0) {
        float4 acc = make_float4(0.f, 0.f, 0.f, 0.f);
        int i = beg;
        for (; i + 1 < end; i += 2) {
            int ua = g_eu[i], ub = g_eu[i + 1];
            float4 h0 = *(const float4*)&g_hn1[(size_t)ua * HID + c];
            float4 h1 = *(const float4*)&g_hn1[(size_t)ub * HID + c];
            acc.x += h0.x + h1.x; acc.y += h0.y + h1.y;
            acc.z += h0.z + h1.z; acc.w += h0.w + h1.w;
        }
        if (i < end) {
            int ua = g_eu[i];
            float4 h0 = *(const float4*)&g_hn1[(size_t)ua * HID + c];
            acc.x += h0.x; acc.y += h0.y; acc.z += h0.z; acc.w += h0.w;
        }
        *(float4*)&g_msum2[(size_t)node * 256 + c] = acc;
    } else {
        float4 qb = *(const float4*)&g_Q[(size_t)node * HID + c];
        float4 acc = make_float4(0.f, 0.f, 0.f, 0.f);
        int i = beg;
        for (; i + 1 < end; i += 2) {
            int ua = g_eu[i], ub = g_eu[i + 1];
            float4 p0 = *(const float4*)&g_P[(size_t)ua * HID + c];
            float4 p1 = *(const float4*)&g_P[(size_t)ub * HID + c];
            acc.x += fmaxf(p0.x + qb.x, 0.f) + fmaxf(p1.x + qb.x, 0.f);
            acc.y += fmaxf(p0.y + qb.y, 0.f) + fmaxf(p1.y + qb.y, 0.f);
            acc.z += fmaxf(p0.z + qb.z, 0.f) + fmaxf(p1.z + qb.z, 0.f);
            acc.w += fmaxf(p0.w + qb.w, 0.f) + fmaxf(p1.w + qb.w, 0.f);
        }
        if (i < end) {
            int ua = g_eu[i];
            float4 p0 = *(const float4*)&g_P[(size_t)ua * HID + c];
            acc.x += fmaxf(p0.x + qb.x, 0.f);
            acc.y += fmaxf(p0.y + qb.y, 0.f);
            acc.z += fmaxf(p0.z + qb.z, 0.f);
            acc.w += fmaxf(p0.w + qb.w, 0.f);
        }
        *(float4*)&g_msum2[(size_t)node * 256 + 128 + c] = acc;
    }
}

// ================= persistent fused node_apply + P/Q projection (work-stealing) ==========
// Phase A: hn_out = relu(concat(hn_in, msum*rdeg) @ Wa + ba)
// Phase B: P = hn_out @ We_top + be;  Q = hn_out @ We_bot   [from smem tile]
template <int KN, int KM, int CTR>
__global__ void __launch_bounds__(128)
fused_node_pq_kernel(const float* __restrict__ hn_in,
                     const float* __restrict__ msum,
                     const float* __restrict__ Wa,
                     const float* __restrict__ ba,
                     const float* __restrict__ We,   // [256,128] row-major
                     const float* __restrict__ be,
                     float* __restrict__ hn_out,
                     float* __restrict__ P,
                     float* __restrict__ Q) {
    constexpr int K = KN + KM;
    __shared__ float smem_buf[K * 18];     // phase A: [K][18]; phase B reuses rows 0..127
    __shared__ float rdeg_s[NPB];
    __shared__ int s_tile;
    float (*xs)[18] = (float(*)[18])smem_buf;
    int tid = threadIdx.x;
    int grp = tid >> 6;
    int jt  = tid & 63;

    // hoisted per-thread invariants
    float ba0 = ba[jt], ba1 = ba[jt + 64];
    float be0 = be[jt], be1 = be[jt + 64];
    const float* Waj = Wa + jt;
    const float* Wej = We + jt;

    while (true) {
        __syncthreads();   // protect xs/rdeg from previous tile's phase-B readers
        if (tid == 0) s_tile = atomicAdd(&g_tilectr[CTR], 1);
        __syncthreads();
        int tile = s_tile;
        if (tile >= N_TILES) break;
        int n0 = tile * NPB;

        if (tid < NPB) {
            int n = n0 + tid;
            float d = (float)max(g_rowptr[n + 1] - g_rowptr[n], 1);
            rdeg_s[tid] = 1.0f / d;
        }
        __syncthreads();

        for (int idx = tid; idx < NPB * K; idx += 128) {
            int ni = idx / K;
            int k  = idx % K;
            int n  = n0 + ni;
            float val;
            if (k < KN) val = hn_in[(size_t)n * KN + k];
            else        val = msum[(size_t)n * KM + (k - KN)] * rdeg_s[ni];
            xs[k][ni] = val;
        }
        __syncthreads();

        // ---- phase A GEMM ----
        {
            ull a0[4], a1[4];
            #pragma unroll
            for (int i = 0; i < 4; i++) { a0[i] = pk2(ba0, ba0); a1[i] = pk2(ba1, ba1); }

            #pragma unroll 4
            for (int k = 0; k < K; k++) {
                float w0 = Waj[k * HID];
                float w1 = Waj[k * HID + 64];
                ull w0d = pk2(w0, w0);
                ull w1d = pk2(w1, w1);
                ull xp[4];
                #pragma unroll
                for (int i = 0; i < 4; i++)
                    xp[i] = *(const ull*)&xs[k][grp * 8 + 2 * i];
                #pragma unroll
                for (int i = 0; i < 4; i++) {
                    FFMA2(a0[i], xp[i], w0d, a0[i]);
                    FFMA2(a1[i], xp[i], w1d, a1[i]);
                }
            }
            __syncthreads();   // all phase-A reads of xs done before overwrite

            #pragma unroll
            for (int i = 0; i < 4; i++) {
                float x0, x1, y0, y1;
                upk2(a0[i], x0, x1);
                upk2(a1[i], y0, y1);
                x0 = fmaxf(x0, 0.f); x1 = fmaxf(x1, 0.f);
                y0 = fmaxf(y0, 0.f); y1 = fmaxf(y1, 0.f);
                int nl = grp * 8 + 2 * i;
                size_t n = (size_t)(n0 + nl);
                hn_out[n * HID + jt]            = x0;
                hn_out[(n + 1) * HID + jt]      = x1;
                hn_out[n * HID + jt + 64]       = y0;
                hn_out[(n + 1) * HID + jt + 64] = y1;
                xs[jt][nl] = x0;       xs[jt][nl + 1] = x1;
                xs[jt + 64][nl] = y0;  xs[jt + 64][nl + 1] = y1;
            }
        }
        __syncthreads();

        // ---- phase B GEMM (pq) from smem tile ----
        {
            ull p0[4], p1[4], q0[4], q1[4];
            #pragma unroll
            for (int i = 0; i < 4; i++) {
                p0[i] = pk2(be0, be0);
                p1[i] = pk2(be1, be1);
                q0[i] = 0ull; q1[i] = 0ull;
            }

            #pragma unroll 2
            for (int k = 0; k < HID; k++) {
                float wt0 = Wej[k * HID];
                float wt1 = Wej[k * HID + 64];
                float wb0 = Wej[(k + HID) * HID];
                float wb1 = Wej[(k + HID) * HID + 64];
                ull wt0d = pk2(wt0, wt0);
                ull wt1d = pk2(wt1, wt1);
                ull wb0d = pk2(wb0, wb0);
                ull wb1d = pk2(wb1, wb1);
                ull xp[4];
                #pragma unroll
                for (int i = 0; i < 4; i++)
                    xp[i] = *(const ull*)&xs[k][grp * 8 + 2 * i];
                #pragma unroll
                for (int i = 0; i < 4; i++) {
                    FFMA2(p0[i], xp[i], wt0d, p0[i]);
                    FFMA2(p1[i], xp[i], wt1d, p1[i]);
                    FFMA2(q0[i], xp[i], wb0d, q0[i]);
                    FFMA2(q1[i], xp[i], wb1d, q1[i]);
                }
            }
            #pragma unroll
            for (int i = 0; i < 4; i++) {
                float x0, x1;
                size_t n = (size_t)(n0 + grp * 8 + 2 * i);
                upk2(p0[i], x0, x1); P[n * HID + jt]      = x0; P[(n + 1) * HID + jt]      = x1;
                upk2(p1[i], x0, x1); P[n * HID + jt + 64] = x0; P[(n + 1) * HID + jt + 64] = x1;
                upk2(q0[i], x0, x1); Q[n * HID + jt]      = x0; Q[(n + 1) * HID + jt]      = x1;
                upk2(q1[i], x0, x1); Q[n * HID + jt + 64] = x0; Q[(n + 1) * HID + jt + 64] = x1;
            }
        }
    }
}

// ================= layer-2 edge, balanced CSR: warp per 4 slots (plain ld/st) =============
#define SLOTS_PER_WARP 4
__global__ void __launch_bounds__(256, 8)
edge2_csr_kernel(float* __restrict__ he2) {
    int gtid = blockIdx.x * blockDim.x + threadIdx.x;
    int warp = gtid >> 5;
    int lane = gtid & 31;
    int s0 = warp * SLOTS_PER_WARP;
    if (s0 >= N_EDGES) return;
    int s1 = min(s0 + SLOTS_PER_WARP, N_EDGES);
    int c = lane * 4;

    int vprev = -1;
    float4 qb = make_float4(0.f, 0.f, 0.f, 0.f);
    #pragma unroll 2
    for (int s = s0; s < s1; s++) {
        int vn = g_ev[s];           // warp-uniform
        if (vn != vprev) {
            qb = *(const float4*)&g_Q[(size_t)vn * HID + c];
            vprev = vn;
        }
        int un  = g_eu[s];
        int eid = g_eid[s];
        float4 p = *(const float4*)&g_P[(size_t)un * HID + c];
        float4 h;
        h.x = fmaxf(p.x + qb.x, 0.f);
        h.y = fmaxf(p.y + qb.y, 0.f);
        h.z = fmaxf(p.z + qb.z, 0.f);
        h.w = fmaxf(p.w + qb.w, 0.f);
        *(float4*)&he2[(size_t)eid * HID + c] = h;
    }
}

// ---------------- launch ----------------
extern "C" void kernel_launch(void* const* d_in, const int* in_sizes, int n_in,
                              void* d_out, int out_size) {
    const float* nfeats = (const float*)d_in[0];
    const float* efeats = (const float*)d_in[1];
    const float* W1a_w  = (const float*)d_in[2];
    const float* W1a_b  = (const float*)d_in[3];
    const float* W1e_w  = (const float*)d_in[4];
    const float* W1e_b  = (const float*)d_in[5];
    const float* W2a_w  = (const float*)d_in[6];
    const float* W2a_b  = (const float*)d_in[7];
    const float* W2e_w  = (const float*)d_in[8];
    const float* W2e_b  = (const float*)d_in[9];
    const int*   u      = (const int*)d_in[10];
    const int*   v      = (const int*)d_in[11];

    float* out = (float*)d_out;
    float* hn2 = out;                          // [N, 128]
    float* he2 = out + (size_t)N_NODES * HID;  // [E, 128]

    void *p_cnt, *p_tc, *p_m1, *p_m2, *p_hn1, *p_P, *p_Q;
    cudaGetSymbolAddress(&p_cnt, g_cnt);
    cudaGetSymbolAddress(&p_tc,  g_tilectr);
    cudaGetSymbolAddress(&p_m1,  g_msum1);
    cudaGetSymbolAddress(&p_m2,  g_msum2);
    cudaGetSymbolAddress(&p_hn1, g_hn1);
    cudaGetSymbolAddress(&p_P,   g_P);
    cudaGetSymbolAddress(&p_Q,   g_Q);
    float* msum1 = (float*)p_m1;
    float* msum2 = (float*)p_m2;
    float* hn1   = (float*)p_hn1;
    float* P     = (float*)p_P;
    float* Q     = (float*)p_Q;

    const int EBLK  = (N_EDGES + 255) / 256;
    const int NWBLK = (N_NODES * 32 + 255) / 256;
    const int A2BLK = (N_NODES * 2 * 32 + 255) / 256;   // 2 warps per node
    const int E2BLK = (((N_EDGES + SLOTS_PER_WARP - 1) / SLOTS_PER_WARP) * 32 + 255) / 256;

    // ---- CSR build (parallel scan; cursor init fused into scan_apply) ----
    cudaMemsetAsync(p_cnt, 0, sizeof(int) * N_NODES, 0);
    cudaMemsetAsync(p_tc,  0, sizeof(int) * 2, 0);
    cnt_kernel<<<EBLK, 256>>>(v);
    part_reduce_kernel<<<N_CHUNKS, 256>>>();
    part_scan_kernel<<<1, 256>>>();
    scan_apply_kernel<<<N_CHUNKS, 256>>>();
    fill_kernel<<<EBLK, 256>>>(u, v);

    // ---- layer 1 ----
    agg1_kernel<<<NWBLK, 256>>>(nfeats, efeats);
    fused_node_pq_kernel<ND_IN, ND_IN + ED_IN, 0><<<PERS_GRID, 128>>>(
        nfeats, msum1, W1a_w, W1a_b, W1e_w, W1e_b, hn1, P, Q);
    agg2_kernel<<<A2BLK, 256>>>();

    // ---- layer 2 ----
    fused_node_pq_kernel<HID, 2 * HID, 1><<<PERS_GRID, 128>>>(
        hn1, msum2, W2a_w, W2a_b, W2e_w, W2e_b, hn2, P, Q);
    edge2_csr_kernel<<<E2BLK, 256>>>(he2);
}

// round 14
// speedup vs baseline: 1.1064x; 1.1064x over previous
#include <cuda_runtime.h>
#include <cuda_bf16.h>
#include <cstddef>

#define N_NODES 50000
#define N_EDGES 800000
#define ND_IN   64
#define ED_IN   64
#define HID     128

typedef unsigned long long ull;

#define SCAN_CHUNK 256
#define N_CHUNKS ((N_NODES + SCAN_CHUNK - 1) / SCAN_CHUNK)   // 196

// ---------------- scratch (allocation-free: __device__ globals) ----------------
__device__ int    g_cnt   [N_NODES];
__device__ int    g_rowptr[N_NODES + 1];
__device__ int    g_cursor[N_NODES];
__device__ int    g_part  [N_CHUNKS];
__device__ int    g_eu    [N_EDGES];   // src node per CSR slot
__device__ int    g_ev    [N_EDGES];   // dst node per CSR slot
__device__ int    g_eid   [N_EDGES];   // original edge id per CSR slot
__device__ float  g_msum1[(size_t)N_NODES * 128];
__device__ float  g_msum2[(size_t)N_NODES * 256];
__device__ float  g_hn1  [(size_t)N_NODES * HID];
__device__ float  g_P    [(size_t)N_NODES * HID];  // hn @ We_top + be (bias folded)
__device__ float  g_Q    [(size_t)N_NODES * HID];  // hn @ We_bot
// packed weights: WaP[k][j] = (Wa[k][j], Wa[k][j+64]);  WeP[k][j] = (We[k][j], We[k][j+64], We[k+128][j], We[k+128][j+64])
__device__ float2 g_Wa1P[192 * 64];
__device__ float2 g_Wa2P[384 * 64];
__device__ float4 g_We1P[128 * 64];
__device__ float4 g_We2P[128 * 64];

// ---------------- packed f32x2 helpers ----------------
__device__ __forceinline__ ull pk2(float x, float y) {
    ull r; asm("mov.b64 %0, {%1, %2};" : "=l"(r) : "f"(x), "f"(y)); return r;
}
__device__ __forceinline__ void upk2(ull p, float& x, float& y) {
    asm("mov.b64 {%0, %1}, %2;" : "=f"(x), "=f"(y) : "l"(p));
}
#define FFMA2(d, a, b, c) \
    asm("fma.rn.f32x2 %0, %1, %2, %3;" : "=l"(d) : "l"(a), "l"(b), "l"(c))

// ================= weight packing =================
__global__ void pack_pair_kernel(const float* __restrict__ W, float2* __restrict__ out, int K) {
    int idx = blockIdx.x * blockDim.x + threadIdx.x;
    if (idx >= K * 64) return;
    int k = idx >> 6, j = idx & 63;
    out[idx] = make_float2(W[k * HID + j], W[k * HID + j + 64]);
}
__global__ void pack_quad_kernel(const float* __restrict__ W, float4* __restrict__ out) {
    int idx = blockIdx.x * blockDim.x + threadIdx.x;   // 128*64
    if (idx >= 128 * 64) return;
    int k = idx >> 6, j = idx & 63;
    out[idx] = make_float4(W[k * HID + j],          W[k * HID + j + 64],
                           W[(k + 128) * HID + j],  W[(k + 128) * HID + j + 64]);
}

// ================= CSR build =================
__global__ void cnt_kernel(const int* __restrict__ v) {
    int e = blockIdx.x * blockDim.x + threadIdx.x;
    if (e < N_EDGES) atomicAdd(&g_cnt[v[e]], 1);
}

// 3-phase parallel scan: chunk reduce -> scan partials (1 block) -> apply
__global__ void part_reduce_kernel() {
    int b = blockIdx.x, t = threadIdx.x;
    int i = b * SCAN_CHUNK + t;
    int x = (i < N_NODES) ? g_cnt[i] : 0;
    __shared__ int ws[8];
    int lane = t & 31, wr = t >> 5;
    #pragma unroll
    for (int d = 16; d > 0; d >>= 1) x += __shfl_down_sync(0xffffffffu, x, d);
    if (lane == 0) ws[wr] = x;
    __syncthreads();
    if (t < 8) {
        int y = ws[t];
        #pragma unroll
        for (int d = 4; d > 0; d >>= 1) y += __shfl_down_sync(0xffu, y, d);
        if (t == 0) g_part[b] = y;
    }
}

__global__ void part_scan_kernel() {
    int t = threadIdx.x;   // 256 threads, N_CHUNKS=196 <= 256
    int x = (t < N_CHUNKS) ? g_part[t] : 0;
    __shared__ int ws[8];
    int lane = t & 31, wr = t >> 5;
    int v = x;
    #pragma unroll
    for (int d = 1; d < 32; d <<= 1) {
        int tt = __shfl_up_sync(0xffffffffu, v, d);
        if (lane >= d) v += tt;
    }
    if (lane == 31) ws[wr] = v;
    __syncthreads();
    if (t < 8) {
        int y = ws[t];
        #pragma unroll
        for (int d = 1; d < 8; d <<= 1) {
            int tt = __shfl_up_sync(0xffu, y, d);
            if (t >= d) y += tt;
        }
        ws[t] = y;
    }
    __syncthreads();
    int incl = v + (wr > 0 ? ws[wr - 1] : 0);
    if (t < N_CHUNKS) g_part[t] = incl - x;           // exclusive chunk offsets
    if (t == N_CHUNKS - 1) g_rowptr[N_NODES] = incl;  // total
}

__global__ void scan_apply_kernel() {
    int b = blockIdx.x, t = threadIdx.x;
    int i = b * SCAN_CHUNK + t;
    int x = (i < N_NODES) ? g_cnt[i] : 0;
    __shared__ int ws[8];
    int lane = t & 31, wr = t >> 5;
    int v = x;
    #pragma unroll
    for (int d = 1; d < 32; d <<= 1) {
        int tt = __shfl_up_sync(0xffffffffu, v, d);
        if (lane >= d) v += tt;
    }
    if (lane == 31) ws[wr] = v;
    __syncthreads();
    if (t < 8) {
        int y = ws[t];
        #pragma unroll
        for (int d = 1; d < 8; d <<= 1) {
            int tt = __shfl_up_sync(0xffu, y, d);
            if (t >= d) y += tt;
        }
        ws[t] = y;
    }
    __syncthreads();
    int excl = v - x + (wr > 0 ? ws[wr - 1] : 0) + g_part[b];
    if (i < N_NODES) {
        g_rowptr[i] = excl;
        g_cursor[i] = excl;   // fill cursors initialized here (no memcpy)
    }
}

__global__ void fill_kernel(const int* __restrict__ u, const int* __restrict__ v) {
    int e = blockIdx.x * blockDim.x + threadIdx.x;
    if (e >= N_EDGES) return;
    int vn = v[e];
    int pos = atomicAdd(&g_cursor[vn], 1);
    g_eu[pos]  = u[e];
    g_ev[pos]  = vn;
    g_eid[pos] = e;
}

// ================= layer-1 aggregation (gather, warp per node, unroll-2) =================
__global__ void __launch_bounds__(256, 8)
agg1_kernel(const float* __restrict__ nf,
            const float* __restrict__ ef) {
    int gtid = blockIdx.x * blockDim.x + threadIdx.x;
    int node = gtid >> 5;
    int lane = gtid & 31;
    if (node >= N_NODES) return;
    int beg = g_rowptr[node], end = g_rowptr[node + 1];
    int c = lane * 4;
    bool isn = (lane < 16);
    const float* base = isn ? nf : ef;
    int coff = isn ? c : (c - ND_IN);
    const int* idxa = isn ? g_eu : g_eid;

    float4 acc = make_float4(0.f, 0.f, 0.f, 0.f);
    int i = beg;
    for (; i + 1 < end; i += 2) {
        int ia = idxa[i];
        int ib = idxa[i + 1];
        float4 t0 = *(const float4*)(base + (size_t)ia * 64 + coff);
        float4 t1 = *(const float4*)(base + (size_t)ib * 64 + coff);
        acc.x += t0.x + t1.x;
        acc.y += t0.y + t1.y;
        acc.z += t0.z + t1.z;
        acc.w += t0.w + t1.w;
    }
    if (i < end) {
        int ia = idxa[i];
        float4 t0 = *(const float4*)(base + (size_t)ia * 64 + coff);
        acc.x += t0.x; acc.y += t0.y; acc.z += t0.z; acc.w += t0.w;
    }
    *(float4*)&g_msum1[(size_t)node * 128 + c] = acc;
}

// ================= layer-2 aggregation, H/E split: 2 warps per node =================
__global__ void __launch_bounds__(256, 8)
agg2_kernel() {
    int gtid = blockIdx.x * blockDim.x + threadIdx.x;
    int warp = gtid >> 5;
    int lane = gtid & 31;
    int node = warp >> 1;
    int half = warp & 1;
    if (node >= N_NODES) return;
    int beg = g_rowptr[node], end = g_rowptr[node + 1];
    int c = lane * 4;

    if (half == 0) {
        float4 acc = make_float4(0.f, 0.f, 0.f, 0.f);
        int i = beg;
        for (; i + 1 < end; i += 2) {
            int ua = g_eu[i], ub = g_eu[i + 1];
            float4 h0 = *(const float4*)&g_hn1[(size_t)ua * HID + c];
            float4 h1 = *(const float4*)&g_hn1[(size_t)ub * HID + c];
            acc.x += h0.x + h1.x; acc.y += h0.y + h1.y;
            acc.z += h0.z + h1.z; acc.w += h0.w + h1.w;
        }
        if (i < end) {
            int ua = g_eu[i];
            float4 h0 = *(const float4*)&g_hn1[(size_t)ua * HID + c];
            acc.x += h0.x; acc.y += h0.y; acc.z += h0.z; acc.w += h0.w;
        }
        *(float4*)&g_msum2[(size_t)node * 256 + c] = acc;
    } else {
        float4 qb = *(const float4*)&g_Q[(size_t)node * HID + c];
        float4 acc = make_float4(0.f, 0.f, 0.f, 0.f);
        int i = beg;
        for (; i + 1 < end; i += 2) {
            int ua = g_eu[i], ub = g_eu[i + 1];
            float4 p0 = *(const float4*)&g_P[(size_t)ua * HID + c];
            float4 p1 = *(const float4*)&g_P[(size_t)ub * HID + c];
            acc.x += fmaxf(p0.x + qb.x, 0.f) + fmaxf(p1.x + qb.x, 0.f);
            acc.y += fmaxf(p0.y + qb.y, 0.f) + fmaxf(p1.y + qb.y, 0.f);
            acc.z += fmaxf(p0.z + qb.z, 0.f) + fmaxf(p1.z + qb.z, 0.f);
            acc.w += fmaxf(p0.w + qb.w, 0.f) + fmaxf(p1.w + qb.w, 0.f);
        }
        if (i < end) {
            int ua = g_eu[i];
            float4 p0 = *(const float4*)&g_P[(size_t)ua * HID + c];
            acc.x += fmaxf(p0.x + qb.x, 0.f);
            acc.y += fmaxf(p0.y + qb.y, 0.f);
            acc.z += fmaxf(p0.z + qb.z, 0.f);
            acc.w += fmaxf(p0.w + qb.w, 0.f);
        }
        *(float4*)&g_msum2[(size_t)node * 256 + 128 + c] = acc;
    }
}

// ================= fused node_apply + P/Q projection (packed weights) =================
template <int KN, int KM>
__global__ void __launch_bounds__(128)
fused_node_pq_kernel(const float* __restrict__ hn_in,
                     const float* __restrict__ msum,
                     const float2* __restrict__ WaP,  // [K][64] pairs
                     const float* __restrict__ ba,
                     const float4* __restrict__ WeP,  // [128][64] quads
                     const float* __restrict__ be,
                     float* __restrict__ hn_out,
                     float* __restrict__ P,
                     float* __restrict__ Q) {
    constexpr int K = KN + KM;
    constexpr int NPB = 16;
    __shared__ float smem_buf[K * 18];
    __shared__ float rdeg_s[NPB];
    float (*xs)[18] = (float(*)[18])smem_buf;
    int n0 = blockIdx.x * NPB;
    int tid = threadIdx.x;

    if (tid < NPB) {
        int n = n0 + tid;
        float d = (float)max(g_rowptr[n + 1] - g_rowptr[n], 1);
        rdeg_s[tid] = 1.0f / d;
    }
    __syncthreads();

    for (int idx = tid; idx < NPB * K; idx += 128) {
        int ni = idx / K;
        int k  = idx % K;
        int n  = n0 + ni;
        float val;
        if (k < KN) val = hn_in[(size_t)n * KN + k];
        else        val = msum[(size_t)n * KM + (k - KN)] * rdeg_s[ni];
        xs[k][ni] = val;
    }
    __syncthreads();

    int grp = tid >> 6;
    int jt  = tid & 63;

    // ---- phase A GEMM (packed pair weights: one LDG.64 per k) ----
    {
        float b0 = ba[jt], b1 = ba[jt + 64];
        ull a0[4], a1[4];
        #pragma unroll
        for (int i = 0; i < 4; i++) { a0[i] = pk2(b0, b0); a1[i] = pk2(b1, b1); }

        const float2* Wj = WaP + jt;
        #pragma unroll 4
        for (int k = 0; k < K; k++) {
            float2 w = Wj[(size_t)k * 64];
            ull w0d = pk2(w.x, w.x);
            ull w1d = pk2(w.y, w.y);
            ull xp[4];
            #pragma unroll
            for (int i = 0; i < 4; i++)
                xp[i] = *(const ull*)&xs[k][grp * 8 + 2 * i];
            #pragma unroll
            for (int i = 0; i < 4; i++) {
                FFMA2(a0[i], xp[i], w0d, a0[i]);
                FFMA2(a1[i], xp[i], w1d, a1[i]);
            }
        }
        __syncthreads();   // all phase-A reads of xs done before overwrite

        #pragma unroll
        for (int i = 0; i < 4; i++) {
            float x0, x1, y0, y1;
            upk2(a0[i], x0, x1);
            upk2(a1[i], y0, y1);
            x0 = fmaxf(x0, 0.f); x1 = fmaxf(x1, 0.f);
            y0 = fmaxf(y0, 0.f); y1 = fmaxf(y1, 0.f);
            int nl = grp * 8 + 2 * i;
            size_t n = (size_t)(n0 + nl);
            hn_out[n * HID + jt]            = x0;
            hn_out[(n + 1) * HID + jt]      = x1;
            hn_out[n * HID + jt + 64]       = y0;
            hn_out[(n + 1) * HID + jt + 64] = y1;
            xs[jt][nl] = x0;       xs[jt][nl + 1] = x1;
            xs[jt + 64][nl] = y0;  xs[jt + 64][nl + 1] = y1;
        }
    }
    __syncthreads();

    // ---- phase B GEMM (packed quad weights: one LDG.128 per k) ----
    {
        float be0 = be[jt], be1 = be[jt + 64];
        ull p0[4], p1[4], q0[4], q1[4];
        #pragma unroll
        for (int i = 0; i < 4; i++) {
            p0[i] = pk2(be0, be0);
            p1[i] = pk2(be1, be1);
            q0[i] = 0ull; q1[i] = 0ull;
        }

        const float4* Wj = WeP + jt;
        #pragma unroll 2
        for (int k = 0; k < HID; k++) {
            float4 w = Wj[(size_t)k * 64];
            ull wt0d = pk2(w.x, w.x);
            ull wt1d = pk2(w.y, w.y);
            ull wb0d = pk2(w.z, w.z);
            ull wb1d = pk2(w.w, w.w);
            ull xp[4];
            #pragma unroll
            for (int i = 0; i < 4; i++)
                xp[i] = *(const ull*)&xs[k][grp * 8 + 2 * i];
            #pragma unroll
            for (int i = 0; i < 4; i++) {
                FFMA2(p0[i], xp[i], wt0d, p0[i]);
                FFMA2(p1[i], xp[i], wt1d, p1[i]);
                FFMA2(q0[i], xp[i], wb0d, q0[i]);
                FFMA2(q1[i], xp[i], wb1d, q1[i]);
            }
        }
        #pragma unroll
        for (int i = 0; i < 4; i++) {
            float x0, x1;
            size_t n = (size_t)(n0 + grp * 8 + 2 * i);
            upk2(p0[i], x0, x1); P[n * HID + jt]      = x0; P[(n + 1) * HID + jt]      = x1;
            upk2(p1[i], x0, x1); P[n * HID + jt + 64] = x0; P[(n + 1) * HID + jt + 64] = x1;
            upk2(q0[i], x0, x1); Q[n * HID + jt]      = x0; Q[(n + 1) * HID + jt]      = x1;
            upk2(q1[i], x0, x1); Q[n * HID + jt + 64] = x0; Q[(n + 1) * HID + jt + 64] = x1;
        }
    }
}

// ================= layer-2 edge, balanced CSR: warp per 4 slots (plain ld/st) =============
#define SLOTS_PER_WARP 4
__global__ void __launch_bounds__(256, 8)
edge2_csr_kernel(float* __restrict__ he2) {
    int gtid = blockIdx.x * blockDim.x + threadIdx.x;
    int warp = gtid >> 5;
    int lane = gtid & 31;
    int s0 = warp * SLOTS_PER_WARP;
    if (s0 >= N_EDGES) return;
    int s1 = min(s0 + SLOTS_PER_WARP, N_EDGES);
    int c = lane * 4;

    int vprev = -1;
    float4 qb = make_float4(0.f, 0.f, 0.f, 0.f);
    #pragma unroll 2
    for (int s = s0; s < s1; s++) {
        int vn = g_ev[s];           // warp-uniform
        if (vn != vprev) {
            qb = *(const float4*)&g_Q[(size_t)vn * HID + c];
            vprev = vn;
        }
        int un  = g_eu[s];
        int eid = g_eid[s];
        float4 p = *(const float4*)&g_P[(size_t)un * HID + c];
        float4 h;
        h.x = fmaxf(p.x + qb.x, 0.f);
        h.y = fmaxf(p.y + qb.y, 0.f);
        h.z = fmaxf(p.z + qb.z, 0.f);
        h.w = fmaxf(p.w + qb.w, 0.f);
        *(float4*)&he2[(size_t)eid * HID + c] = h;
    }
}

// ---------------- launch ----------------
extern "C" void kernel_launch(void* const* d_in, const int* in_sizes, int n_in,
                              void* d_out, int out_size) {
    const float* nfeats = (const float*)d_in[0];
    const float* efeats = (const float*)d_in[1];
    const float* W1a_w  = (const float*)d_in[2];
    const float* W1a_b  = (const float*)d_in[3];
    const float* W1e_w  = (const float*)d_in[4];
    const float* W1e_b  = (const float*)d_in[5];
    const float* W2a_w  = (const float*)d_in[6];
    const float* W2a_b  = (const float*)d_in[7];
    const float* W2e_w  = (const float*)d_in[8];
    const float* W2e_b  = (const float*)d_in[9];
    const int*   u      = (const int*)d_in[10];
    const int*   v      = (const int*)d_in[11];

    float* out = (float*)d_out;
    float* hn2 = out;                          // [N, 128]
    float* he2 = out + (size_t)N_NODES * HID;  // [E, 128]

    void *p_cnt, *p_m1, *p_m2, *p_hn1, *p_P, *p_Q;
    void *p_Wa1P, *p_Wa2P, *p_We1P, *p_We2P;
    cudaGetSymbolAddress(&p_cnt,  g_cnt);
    cudaGetSymbolAddress(&p_m1,   g_msum1);
    cudaGetSymbolAddress(&p_m2,   g_msum2);
    cudaGetSymbolAddress(&p_hn1,  g_hn1);
    cudaGetSymbolAddress(&p_P,    g_P);
    cudaGetSymbolAddress(&p_Q,    g_Q);
    cudaGetSymbolAddress(&p_Wa1P, g_Wa1P);
    cudaGetSymbolAddress(&p_Wa2P, g_Wa2P);
    cudaGetSymbolAddress(&p_We1P, g_We1P);
    cudaGetSymbolAddress(&p_We2P, g_We2P);
    float* msum1 = (float*)p_m1;
    float* msum2 = (float*)p_m2;
    float* hn1   = (float*)p_hn1;
    float* P     = (float*)p_P;
    float* Q     = (float*)p_Q;
    float2* Wa1P = (float2*)p_Wa1P;
    float2* Wa2P = (float2*)p_Wa2P;
    float4* We1P = (float4*)p_We1P;
    float4* We2P = (float4*)p_We2P;

    const int EBLK  = (N_EDGES + 255) / 256;
    const int NWBLK = (N_NODES * 32 + 255) / 256;
    const int A2BLK = (N_NODES * 2 * 32 + 255) / 256;   // 2 warps per node
    const int GBLK  = N_NODES / 16;                      // 3125
    const int E2BLK = (((N_EDGES + SLOTS_PER_WARP - 1) / SLOTS_PER_WARP) * 32 + 255) / 256;

    // ---- weight packing (independent of graph topology) ----
    pack_pair_kernel<<<(192 * 64 + 255) / 256, 256>>>(W1a_w, Wa1P, 192);
    pack_pair_kernel<<<(384 * 64 + 255) / 256, 256>>>(W2a_w, Wa2P, 384);
    pack_quad_kernel<<<(128 * 64 + 255) / 256, 256>>>(W1e_w, We1P);
    pack_quad_kernel<<<(128 * 64 + 255) / 256, 256>>>(W2e_w, We2P);

    // ---- CSR build (parallel scan; cursor init fused into scan_apply) ----
    cudaMemsetAsync(p_cnt, 0, sizeof(int) * N_NODES, 0);
    cnt_kernel<<<EBLK, 256>>>(v);
    part_reduce_kernel<<<N_CHUNKS, 256>>>();
    part_scan_kernel<<<1, 256>>>();
    scan_apply_kernel<<<N_CHUNKS, 256>>>();
    fill_kernel<<<EBLK, 256>>>(u, v);

    // ---- layer 1 ----
    agg1_kernel<<<NWBLK, 256>>>(nfeats, efeats);
    fused_node_pq_kernel<ND_IN, ND_IN + ED_IN><<<GBLK, 128>>>(
        nfeats, msum1, Wa1P, W1a_b, We1P, W1e_b, hn1, P, Q);
    agg2_kernel<<<A2BLK, 256>>>();

    // ---- layer 2 ----
    fused_node_pq_kernel<HID, 2 * HID><<<GBLK, 128>>>(
        hn1, msum2, Wa2P, W2a_b, We2P, W2e_b, hn2, P, Q);
    edge2_csr_kernel<<<E2BLK, 256>>>(he2);
}